// round 2
// baseline (speedup 1.0000x reference)
#include <cuda_runtime.h>
#include <math.h>

// Problem constants (fixed by the dataset)
#define LDIM 128        // nodes per sentence
#define HDIM 128        // hidden
#define NBS  2048       // B*S sentences
#define SST  132        // smem row stride (pad to dodge conflicts)
#define NUM_LOOP 10

// ---------------- device scratch (no cudaMalloc allowed) ----------------
__device__ float g_Gt[128 * 384];    // (gnn_w @ W_ih^T), row-major [k][j]
__device__ float g_Whht[128 * 384];  // W_hh^T, [k][j] = W_hh[j][k]
__device__ float g_u[384];           // gnn_b @ W_ih^T
__device__ float g_m1t[128 * 128];   // mW1^T
__device__ float g_m2t[128 * 128];   // mW2^T

// ---------------- prep kernels (run every launch; deterministic) --------
__global__ void prep_gemm(const float* __restrict__ gnn_w,
                          const float* __restrict__ W_ih,
                          const float* __restrict__ gnn_b) {
    int t = blockIdx.x * blockDim.x + threadIdx.x;
    if (t < 128 * 384) {
        int k = t / 384, j = t % 384;
        const float* wr = gnn_w + k * 128;
        const float* ir = W_ih + j * 128;
        float acc = 0.f;
#pragma unroll 4
        for (int m = 0; m < 128; ++m) acc = fmaf(wr[m], ir[m], acc);
        g_Gt[t] = acc;
        if (t < 384) {
            const float* ir2 = W_ih + t * 128;
            float a2 = 0.f;
#pragma unroll 4
            for (int m = 0; m < 128; ++m) a2 = fmaf(gnn_b[m], ir2[m], a2);
            g_u[t] = a2;
        }
    }
}

__global__ void prep_trans(const float* __restrict__ W_hh,
                           const float* __restrict__ mW1,
                           const float* __restrict__ mW2) {
    int t = blockIdx.x * blockDim.x + threadIdx.x;
    if (t < 128 * 384) {
        int k = t / 384, j = t % 384;
        g_Whht[t] = W_hh[j * 128 + k];
    } else if (t < 128 * 384 + 128 * 128) {
        int q = t - 128 * 384;
        int k = q / 128, j = q % 128;
        g_m1t[q] = mW1[j * 128 + k];
    } else if (t < 128 * 384 + 2 * 128 * 128) {
        int q = t - 128 * 384 - 128 * 128;
        int k = q / 128, j = q % 128;
        g_m2t[q] = mW2[j * 128 + k];
    }
}

// ---------------- register-tiled GEMM: C[128,128] += A_smem[128,128] @ B_glb[128,ldb] ----
// Thread (tx,ty) in 16x16 grid owns 8x8 C tile: rows ty*8.., cols tx*8..
__device__ __forceinline__ void gemm1(const float* __restrict__ A,
                                      const float* __restrict__ B,
                                      int ldb,
                                      float* __restrict__ acc,
                                      int tx, int ty) {
    const float* Ar = A + ty * 8 * SST;
    const float* Bp = B + tx * 8;
#pragma unroll 2
    for (int k4 = 0; k4 < 128; k4 += 4) {
        float4 a4[8];
#pragma unroll
        for (int i = 0; i < 8; ++i)
            a4[i] = *(const float4*)(Ar + i * SST + k4);
        float4 b0[4], b1[4];
#pragma unroll
        for (int kk = 0; kk < 4; ++kk) {
            b0[kk] = *(const float4*)(Bp + (k4 + kk) * ldb);
            b1[kk] = *(const float4*)(Bp + (k4 + kk) * ldb + 4);
        }
#pragma unroll
        for (int kk = 0; kk < 4; ++kk) {
            float b[8] = {b0[kk].x, b0[kk].y, b0[kk].z, b0[kk].w,
                          b1[kk].x, b1[kk].y, b1[kk].z, b1[kk].w};
#pragma unroll
            for (int i = 0; i < 8; ++i) {
                float a = (kk == 0) ? a4[i].x : (kk == 1) ? a4[i].y
                         : (kk == 2) ? a4[i].z : a4[i].w;
#pragma unroll
                for (int j = 0; j < 8; ++j)
                    acc[i * 8 + j] = fmaf(a, b[j], acc[i * 8 + j]);
            }
        }
    }
}

__device__ __forceinline__ float sigmoidf_(float x) {
    return 1.0f / (1.0f + expf(-x));
}

// ---------------- the fused GNN kernel: one CTA per (b,s) ----------------
__global__ void __launch_bounds__(256, 1)
gnn_main(const int* __restrict__ input_var,
         const float* __restrict__ adj,
         const float* __restrict__ emb,
         const float* __restrict__ b_ih,
         const float* __restrict__ b_hh,
         const float* __restrict__ mb1,
         const float* __restrict__ mb2,
         const float* __restrict__ mW3,
         const float* __restrict__ mb3,
         float* __restrict__ out) {
    extern __shared__ float sm[];
    float* nf = sm;                       // [128][SST] node features (persistent)
    float* sb = nf + LDIM * SST;          // [128][SST] s = A@nf / h1
    float* Rb = sb + LDIM * SST;          // [128][SST] r -> n / h2
    unsigned* mask = (unsigned*)(Rb + LDIM * SST);  // [128][4] adjacency bitmask
    float* deg = (float*)(mask + LDIM * 4);         // [128] row degrees

    const int tid = threadIdx.x;
    const int tx = tid & 15, ty = tid >> 4;
    const int lane = tid & 31, warp = tid >> 5;
    const int bs = blockIdx.x;
    const int row0 = ty * 8, col0 = tx * 8;

    // ---- embedding gather: nf[l][:] = emb[input_var[bs][l]][:]
    {
        const int* iv = input_var + bs * LDIM;
        for (int r = 0; r < 16; ++r) {
            int l = warp * 16 + r;
            int idx = iv[l];
            float4 v = ((const float4*)(emb + (size_t)idx * HDIM))[lane];
            *(float4*)(nf + l * SST + lane * 4) = v;
        }
    }

    // ---- adjacency -> bitmask (each thread builds 2 of the 512 words)
    {
        const float4* ab = (const float4*)(adj + (size_t)bs * LDIM * LDIM);
#pragma unroll
        for (int ww = 0; ww < 2; ++ww) {
            int w = tid * 2 + ww;
            int l = w >> 2, part = w & 3;
            const float4* p = ab + (l * LDIM + part * 32) / 4;
            unsigned m = 0;
#pragma unroll
            for (int q = 0; q < 8; ++q) {
                float4 v = p[q];
                m |= (v.x > 0.5f ? 1u : 0u) << (q * 4 + 0);
                m |= (v.y > 0.5f ? 1u : 0u) << (q * 4 + 1);
                m |= (v.z > 0.5f ? 1u : 0u) << (q * 4 + 2);
                m |= (v.w > 0.5f ? 1u : 0u) << (q * 4 + 3);
            }
            mask[w] = m;
        }
    }
    __syncthreads();
    if (tid < LDIM) {
        deg[tid] = (float)(__popc(mask[tid * 4 + 0]) + __popc(mask[tid * 4 + 1]) +
                           __popc(mask[tid * 4 + 2]) + __popc(mask[tid * 4 + 3]));
    }
    __syncthreads();

    float acc[64], accB[64];

    // ---- 10 GRU iterations, fully in SMEM ----
    for (int it = 0; it < NUM_LOOP; ++it) {
        // s = A @ nf via bitmask gather (warp owns 16 rows; lane owns 4 h cols)
        for (int r = 0; r < 16; ++r) {
            int l = warp * 16 + r;
            float4 a = make_float4(0.f, 0.f, 0.f, 0.f);
#pragma unroll
            for (int w4 = 0; w4 < 4; ++w4) {
                unsigned m = mask[l * 4 + w4];
                while (m) {
                    int c = w4 * 32 + __ffs((int)m) - 1;
                    m &= m - 1;
                    float4 v = *(const float4*)(nf + c * SST + lane * 4);
                    a.x += v.x; a.y += v.y; a.z += v.z; a.w += v.w;
                }
            }
            *(float4*)(sb + l * SST + lane * 4) = a;
        }
        __syncthreads();

        // ---- R gate: r = sigmoid(s@G_r + deg*u_r + b_ih_r + nf@Whh_r + b_hh_r)
#pragma unroll
        for (int i = 0; i < 64; ++i) acc[i] = 0.f;
        gemm1(sb, g_Gt + 0, 384, acc, tx, ty);
        gemm1(nf, g_Whht + 0, 384, acc, tx, ty);
#pragma unroll
        for (int i = 0; i < 8; ++i) {
            int l = row0 + i;
            float dg = deg[l];
#pragma unroll
            for (int j = 0; j < 8; ++j) {
                int h = col0 + j;
                float v = acc[i * 8 + j] + dg * g_u[h] + b_ih[h] + b_hh[h];
                Rb[l * SST + h] = sigmoidf_(v);
            }
        }

        // ---- n gate: n = tanh( (s@G_n + deg*u_n + b_ih_n) + r * (nf@Whh_n + b_hh_n) )
#pragma unroll
        for (int i = 0; i < 64; ++i) { acc[i] = 0.f; accB[i] = 0.f; }
        gemm1(sb, g_Gt + 256, 384, acc, tx, ty);
        gemm1(nf, g_Whht + 256, 384, accB, tx, ty);
#pragma unroll
        for (int i = 0; i < 8; ++i) {
            int l = row0 + i;
            float dg = deg[l];
#pragma unroll
            for (int j = 0; j < 8; ++j) {
                int h = col0 + j;
                float ni = acc[i * 8 + j] + dg * g_u[256 + h] + b_ih[256 + h];
                float hn = accB[i * 8 + j] + b_hh[256 + h];
                float r = Rb[l * SST + h];          // same-thread coords: no race
                Rb[l * SST + h] = tanhf(ni + r * hn);  // overwrite r with n
            }
        }

        // ---- Z gate + state update: nf = n + z*(nf - n)
#pragma unroll
        for (int i = 0; i < 64; ++i) acc[i] = 0.f;
        gemm1(sb, g_Gt + 128, 384, acc, tx, ty);
        gemm1(nf, g_Whht + 128, 384, acc, tx, ty);
        __syncthreads();  // all reads of nf/sb complete before nf is overwritten
#pragma unroll
        for (int i = 0; i < 8; ++i) {
            int l = row0 + i;
            float dg = deg[l];
#pragma unroll
            for (int j = 0; j < 8; ++j) {
                int h = col0 + j;
                float v = acc[i * 8 + j] + dg * g_u[128 + h] + b_ih[128 + h] + b_hh[128 + h];
                float z = sigmoidf_(v);
                float n = Rb[l * SST + h];
                float old = nf[l * SST + h];
                nf[l * SST + h] = n + z * (old - n);
            }
        }
        __syncthreads();
    }

    // ---- mention MLP: h1 = tanh(nf@mW1^T+b1); h2 = tanh(h1@mW2^T+b2); tanh(h2@mW3^T+b3)
#pragma unroll
    for (int i = 0; i < 64; ++i) acc[i] = 0.f;
    gemm1(nf, g_m1t, 128, acc, tx, ty);
#pragma unroll
    for (int i = 0; i < 8; ++i)
#pragma unroll
        for (int j = 0; j < 8; ++j)
            sb[(row0 + i) * SST + col0 + j] = tanhf(acc[i * 8 + j] + mb1[col0 + j]);
    __syncthreads();

#pragma unroll
    for (int i = 0; i < 64; ++i) acc[i] = 0.f;
    gemm1(sb, g_m2t, 128, acc, tx, ty);
#pragma unroll
    for (int i = 0; i < 8; ++i)
#pragma unroll
        for (int j = 0; j < 8; ++j)
            Rb[(row0 + i) * SST + col0 + j] = tanhf(acc[i * 8 + j] + mb2[col0 + j]);
    __syncthreads();

    if (tid < LDIM) {
        float a = mb3[0];
#pragma unroll 4
        for (int h = 0; h < HDIM; ++h)
            a = fmaf(Rb[tid * SST + h], mW3[h], a);
        out[bs * LDIM + tid] = tanhf(a);
    }
}

// ---------------- launch ----------------
extern "C" void kernel_launch(void* const* d_in, const int* in_sizes, int n_in,
                              void* d_out, int out_size) {
    const int*   input_var = (const int*)  d_in[0];
    const float* adjacency = (const float*)d_in[1];
    const float* emb       = (const float*)d_in[2];
    const float* gnn_w     = (const float*)d_in[3];
    const float* gnn_b     = (const float*)d_in[4];
    const float* W_ih      = (const float*)d_in[5];
    const float* W_hh      = (const float*)d_in[6];
    const float* b_ih      = (const float*)d_in[7];
    const float* b_hh      = (const float*)d_in[8];
    const float* mW1       = (const float*)d_in[9];
    const float* mb1       = (const float*)d_in[10];
    const float* mW2       = (const float*)d_in[11];
    const float* mb2       = (const float*)d_in[12];
    const float* mW3       = (const float*)d_in[13];
    const float* mb3       = (const float*)d_in[14];
    float* out = (float*)d_out;

    // prep: fused weight products + transposes (deterministic, recomputed every call)
    prep_gemm<<<(128 * 384 + 255) / 256, 256>>>(gnn_w, W_ih, gnn_b);
    prep_trans<<<(128 * 384 + 2 * 128 * 128 + 255) / 256, 256>>>(W_hh, mW1, mW2);

    const int smem_bytes = (3 * LDIM * SST) * 4 + LDIM * 4 * 4 + LDIM * 4;
    cudaFuncSetAttribute(gnn_main, cudaFuncAttributeMaxDynamicSharedMemorySize, smem_bytes);
    gnn_main<<<NBS, 256, smem_bytes>>>(input_var, adjacency, emb,
                                       b_ih, b_hh, mb1, mb2, mW3, mb3, out);
}

// round 3
// speedup vs baseline: 1.5168x; 1.5168x over previous
#include <cuda_runtime.h>
#include <math.h>

// Problem constants (fixed by the dataset)
#define LDIM 128        // nodes per sentence
#define HDIM 128        // hidden
#define NBS  2048       // B*S sentences
#define SST  132        // smem row stride (pad to dodge conflicts)
#define NUM_LOOP 10

// ---------------- device scratch (no cudaMalloc allowed) ----------------
__device__ float g_Gt[128 * 384];    // (gnn_w @ W_ih^T), row-major [k][j]
__device__ float g_Whht[128 * 384];  // W_hh^T, [k][j] = W_hh[j][k]
__device__ float g_u[384];           // gnn_b @ W_ih^T
__device__ float g_m1t[128 * 128];   // mW1^T
__device__ float g_m2t[128 * 128];   // mW2^T

// ---------------- prep kernels (run every launch; deterministic) --------
__global__ void prep_gemm(const float* __restrict__ gnn_w,
                          const float* __restrict__ W_ih,
                          const float* __restrict__ gnn_b) {
    int t = blockIdx.x * blockDim.x + threadIdx.x;
    if (t < 128 * 384) {
        int k = t / 384, j = t % 384;
        const float* wr = gnn_w + k * 128;
        const float* ir = W_ih + j * 128;
        float acc = 0.f;
#pragma unroll 4
        for (int m = 0; m < 128; ++m) acc = fmaf(wr[m], ir[m], acc);
        g_Gt[t] = acc;
        if (t < 384) {
            const float* ir2 = W_ih + t * 128;
            float a2 = 0.f;
#pragma unroll 4
            for (int m = 0; m < 128; ++m) a2 = fmaf(gnn_b[m], ir2[m], a2);
            g_u[t] = a2;
        }
    }
}

__global__ void prep_trans(const float* __restrict__ W_hh,
                           const float* __restrict__ mW1,
                           const float* __restrict__ mW2) {
    int t = blockIdx.x * blockDim.x + threadIdx.x;
    if (t < 128 * 384) {
        int k = t / 384, j = t % 384;
        g_Whht[t] = W_hh[j * 128 + k];
    } else if (t < 128 * 384 + 128 * 128) {
        int q = t - 128 * 384;
        int k = q / 128, j = q % 128;
        g_m1t[q] = mW1[j * 128 + k];
    } else if (t < 128 * 384 + 2 * 128 * 128) {
        int q = t - 128 * 384 - 128 * 128;
        int k = q / 128, j = q % 128;
        g_m2t[q] = mW2[j * 128 + k];
    }
}

// ---------------- register-tiled GEMM: C[128,128] += A_smem[128,128] @ B_glb[128,ldb] ----
// Thread (tx,ty) in 16x16 grid owns 8x8 C tile: rows ty*8.., cols tx*8..
__device__ __forceinline__ void gemm1(const float* __restrict__ A,
                                      const float* __restrict__ B,
                                      int ldb,
                                      float* __restrict__ acc,
                                      int tx, int ty) {
    const float* Ar = A + ty * 8 * SST;
    const float* Bp = B + tx * 8;
#pragma unroll 2
    for (int k4 = 0; k4 < 128; k4 += 4) {
        float4 a4[8];
#pragma unroll
        for (int i = 0; i < 8; ++i)
            a4[i] = *(const float4*)(Ar + i * SST + k4);
        float4 b0[4], b1[4];
#pragma unroll
        for (int kk = 0; kk < 4; ++kk) {
            b0[kk] = *(const float4*)(Bp + (k4 + kk) * ldb);
            b1[kk] = *(const float4*)(Bp + (k4 + kk) * ldb + 4);
        }
#pragma unroll
        for (int kk = 0; kk < 4; ++kk) {
            float b[8] = {b0[kk].x, b0[kk].y, b0[kk].z, b0[kk].w,
                          b1[kk].x, b1[kk].y, b1[kk].z, b1[kk].w};
#pragma unroll
            for (int i = 0; i < 8; ++i) {
                float a = (kk == 0) ? a4[i].x : (kk == 1) ? a4[i].y
                         : (kk == 2) ? a4[i].z : a4[i].w;
#pragma unroll
                for (int j = 0; j < 8; ++j)
                    acc[i * 8 + j] = fmaf(a, b[j], acc[i * 8 + j]);
            }
        }
    }
}

__device__ __forceinline__ float sigmoidf_(float x) {
    return 1.0f / (1.0f + expf(-x));
}

// ---------------- the fused GNN kernel: one CTA per (b,s) ----------------
__global__ void __launch_bounds__(256, 1)
gnn_main(const int* __restrict__ input_var,
         const float* __restrict__ adj,
         const float* __restrict__ emb,
         const float* __restrict__ b_ih,
         const float* __restrict__ b_hh,
         const float* __restrict__ mb1,
         const float* __restrict__ mb2,
         const float* __restrict__ mW3,
         const float* __restrict__ mb3,
         float* __restrict__ out) {
    extern __shared__ float sm[];
    float* nf = sm;                       // [128][SST] node features (persistent)
    float* sb = nf + LDIM * SST;          // [128][SST] s = A@nf / h1
    float* Rb = sb + LDIM * SST;          // [128][SST] r -> n / h2
    unsigned* mask = (unsigned*)(Rb + LDIM * SST);  // [128][4] adjacency bitmask
    float* deg = (float*)(mask + LDIM * 4);         // [128] row degrees

    const int tid = threadIdx.x;
    const int tx = tid & 15, ty = tid >> 4;
    const int lane = tid & 31, warp = tid >> 5;
    const int bs = blockIdx.x;
    const int row0 = ty * 8, col0 = tx * 8;

    // ---- embedding gather: nf[l][:] = emb[input_var[bs][l]][:]
    {
        const int* iv = input_var + bs * LDIM;
        for (int r = 0; r < 16; ++r) {
            int l = warp * 16 + r;
            int idx = iv[l];
            float4 v = ((const float4*)(emb + (size_t)idx * HDIM))[lane];
            *(float4*)(nf + l * SST + lane * 4) = v;
        }
    }

    // ---- adjacency -> bitmask (each thread builds 2 of the 512 words)
    {
        const float4* ab = (const float4*)(adj + (size_t)bs * LDIM * LDIM);
#pragma unroll
        for (int ww = 0; ww < 2; ++ww) {
            int w = tid * 2 + ww;
            int l = w >> 2, part = w & 3;
            const float4* p = ab + (l * LDIM + part * 32) / 4;
            unsigned m = 0;
#pragma unroll
            for (int q = 0; q < 8; ++q) {
                float4 v = p[q];
                m |= (v.x > 0.5f ? 1u : 0u) << (q * 4 + 0);
                m |= (v.y > 0.5f ? 1u : 0u) << (q * 4 + 1);
                m |= (v.z > 0.5f ? 1u : 0u) << (q * 4 + 2);
                m |= (v.w > 0.5f ? 1u : 0u) << (q * 4 + 3);
            }
            mask[w] = m;
        }
    }
    __syncthreads();
    if (tid < LDIM) {
        deg[tid] = (float)(__popc(mask[tid * 4 + 0]) + __popc(mask[tid * 4 + 1]) +
                           __popc(mask[tid * 4 + 2]) + __popc(mask[tid * 4 + 3]));
    }
    __syncthreads();

    float acc[64], accB[64];

    // ---- 10 GRU iterations, fully in SMEM ----
    for (int it = 0; it < NUM_LOOP; ++it) {
        // s = A @ nf via bitmask gather (warp owns 16 rows; lane owns 4 h cols)
        for (int r = 0; r < 16; ++r) {
            int l = warp * 16 + r;
            float4 a = make_float4(0.f, 0.f, 0.f, 0.f);
#pragma unroll
            for (int w4 = 0; w4 < 4; ++w4) {
                unsigned m = mask[l * 4 + w4];
                while (m) {
                    int c = w4 * 32 + __ffs((int)m) - 1;
                    m &= m - 1;
                    float4 v = *(const float4*)(nf + c * SST + lane * 4);
                    a.x += v.x; a.y += v.y; a.z += v.z; a.w += v.w;
                }
            }
            *(float4*)(sb + l * SST + lane * 4) = a;
        }
        __syncthreads();

        // ---- R gate: r = sigmoid(s@G_r + deg*u_r + b_ih_r + nf@Whh_r + b_hh_r)
#pragma unroll
        for (int i = 0; i < 64; ++i) acc[i] = 0.f;
        gemm1(sb, g_Gt + 0, 384, acc, tx, ty);
        gemm1(nf, g_Whht + 0, 384, acc, tx, ty);
#pragma unroll
        for (int i = 0; i < 8; ++i) {
            int l = row0 + i;
            float dg = deg[l];
#pragma unroll
            for (int j = 0; j < 8; ++j) {
                int h = col0 + j;
                float v = acc[i * 8 + j] + dg * g_u[h] + b_ih[h] + b_hh[h];
                Rb[l * SST + h] = sigmoidf_(v);
            }
        }

        // ---- n gate: n = tanh( (s@G_n + deg*u_n + b_ih_n) + r * (nf@Whh_n + b_hh_n) )
#pragma unroll
        for (int i = 0; i < 64; ++i) { acc[i] = 0.f; accB[i] = 0.f; }
        gemm1(sb, g_Gt + 256, 384, acc, tx, ty);
        gemm1(nf, g_Whht + 256, 384, accB, tx, ty);
#pragma unroll
        for (int i = 0; i < 8; ++i) {
            int l = row0 + i;
            float dg = deg[l];
#pragma unroll
            for (int j = 0; j < 8; ++j) {
                int h = col0 + j;
                float ni = acc[i * 8 + j] + dg * g_u[256 + h] + b_ih[256 + h];
                float hn = accB[i * 8 + j] + b_hh[256 + h];
                float r = Rb[l * SST + h];          // same-thread coords: no race
                Rb[l * SST + h] = tanhf(ni + r * hn);  // overwrite r with n
            }
        }

        // ---- Z gate + state update: nf = n + z*(nf - n)
#pragma unroll
        for (int i = 0; i < 64; ++i) acc[i] = 0.f;
        gemm1(sb, g_Gt + 128, 384, acc, tx, ty);
        gemm1(nf, g_Whht + 128, 384, acc, tx, ty);
        __syncthreads();  // all reads of nf/sb complete before nf is overwritten
#pragma unroll
        for (int i = 0; i < 8; ++i) {
            int l = row0 + i;
            float dg = deg[l];
#pragma unroll
            for (int j = 0; j < 8; ++j) {
                int h = col0 + j;
                float v = acc[i * 8 + j] + dg * g_u[128 + h] + b_ih[128 + h] + b_hh[128 + h];
                float z = sigmoidf_(v);
                float n = Rb[l * SST + h];
                float old = nf[l * SST + h];
                nf[l * SST + h] = n + z * (old - n);
            }
        }
        __syncthreads();
    }

    // ---- mention MLP: h1 = tanh(nf@mW1^T+b1); h2 = tanh(h1@mW2^T+b2); tanh(h2@mW3^T+b3)
#pragma unroll
    for (int i = 0; i < 64; ++i) acc[i] = 0.f;
    gemm1(nf, g_m1t, 128, acc, tx, ty);
#pragma unroll
    for (int i = 0; i < 8; ++i)
#pragma unroll
        for (int j = 0; j < 8; ++j)
            sb[(row0 + i) * SST + col0 + j] = tanhf(acc[i * 8 + j] + mb1[col0 + j]);
    __syncthreads();

#pragma unroll
    for (int i = 0; i < 64; ++i) acc[i] = 0.f;
    gemm1(sb, g_m2t, 128, acc, tx, ty);
#pragma unroll
    for (int i = 0; i < 8; ++i)
#pragma unroll
        for (int j = 0; j < 8; ++j)
            Rb[(row0 + i) * SST + col0 + j] = tanhf(acc[i * 8 + j] + mb2[col0 + j]);
    __syncthreads();

    if (tid < LDIM) {
        float a = mb3[0];
#pragma unroll 4
        for (int h = 0; h < HDIM; ++h)
            a = fmaf(Rb[tid * SST + h], mW3[h], a);
        out[bs * LDIM + tid] = tanhf(a);
    }
}

// ---------------- launch ----------------
extern "C" void kernel_launch(void* const* d_in, const int* in_sizes, int n_in,
                              void* d_out, int out_size) {
    const int*   input_var = (const int*)  d_in[0];
    const float* adjacency = (const float*)d_in[1];
    const float* emb       = (const float*)d_in[2];
    const float* gnn_w     = (const float*)d_in[3];
    const float* gnn_b     = (const float*)d_in[4];
    const float* W_ih      = (const float*)d_in[5];
    const float* W_hh      = (const float*)d_in[6];
    const float* b_ih      = (const float*)d_in[7];
    const float* b_hh      = (const float*)d_in[8];
    const float* mW1       = (const float*)d_in[9];
    const float* mb1       = (const float*)d_in[10];
    const float* mW2       = (const float*)d_in[11];
    const float* mb2       = (const float*)d_in[12];
    const float* mW3       = (const float*)d_in[13];
    const float* mb3       = (const float*)d_in[14];
    float* out = (float*)d_out;

    // prep: fused weight products + transposes (deterministic, recomputed every call)
    prep_gemm<<<(128 * 384 + 255) / 256, 256>>>(gnn_w, W_ih, gnn_b);
    prep_trans<<<(128 * 384 + 2 * 128 * 128 + 255) / 256, 256>>>(W_hh, mW1, mW2);

    const int smem_bytes = (3 * LDIM * SST) * 4 + LDIM * 4 * 4 + LDIM * 4;
    cudaFuncSetAttribute(gnn_main, cudaFuncAttributeMaxDynamicSharedMemorySize, smem_bytes);
    gnn_main<<<NBS, 256, smem_bytes>>>(input_var, adjacency, emb,
                                       b_ih, b_hh, mb1, mb2, mW3, mb3, out);
}

// round 4
// speedup vs baseline: 1.5938x; 1.0508x over previous
#include <cuda_runtime.h>
#include <math.h>

// Problem constants (fixed by the dataset)
#define LDIM 128        // nodes per sentence
#define HDIM 128        // hidden
#define NBS  2048       // B*S sentences
#define SST  132        // smem row stride (pad to dodge conflicts)
#define NUM_LOOP 10

// ---------------- device scratch (no cudaMalloc allowed) ----------------
__device__ float g_Gt[128 * 384];    // (gnn_w @ W_ih^T), row-major [k][j]
__device__ float g_Whht[128 * 384];  // W_hh^T, [k][j] = W_hh[j][k]
__device__ float g_u[384];           // gnn_b @ W_ih^T
__device__ float g_m1t[128 * 128];   // mW1^T
__device__ float g_m2t[128 * 128];   // mW2^T

// ---------------- prep kernels (run every launch; deterministic) --------
__global__ void prep_gemm(const float* __restrict__ gnn_w,
                          const float* __restrict__ W_ih,
                          const float* __restrict__ gnn_b) {
    int t = blockIdx.x * blockDim.x + threadIdx.x;
    if (t < 128 * 384) {
        int k = t / 384, j = t % 384;
        const float* wr = gnn_w + k * 128;
        const float* ir = W_ih + j * 128;
        float acc = 0.f;
#pragma unroll 4
        for (int m = 0; m < 128; ++m) acc = fmaf(wr[m], ir[m], acc);
        g_Gt[t] = acc;
        if (t < 384) {
            const float* ir2 = W_ih + t * 128;
            float a2 = 0.f;
#pragma unroll 4
            for (int m = 0; m < 128; ++m) a2 = fmaf(gnn_b[m], ir2[m], a2);
            g_u[t] = a2;
        }
    }
}

__global__ void prep_trans(const float* __restrict__ W_hh,
                           const float* __restrict__ mW1,
                           const float* __restrict__ mW2) {
    int t = blockIdx.x * blockDim.x + threadIdx.x;
    if (t < 128 * 384) {
        int k = t / 384, j = t % 384;
        g_Whht[t] = W_hh[j * 128 + k];
    } else if (t < 128 * 384 + 128 * 128) {
        int q = t - 128 * 384;
        int k = q / 128, j = q % 128;
        g_m1t[q] = mW1[j * 128 + k];
    } else if (t < 128 * 384 + 2 * 128 * 128) {
        int q = t - 128 * 384 - 128 * 128;
        int k = q / 128, j = q % 128;
        g_m2t[q] = mW2[j * 128 + k];
    }
}

// ---------------- register-tiled GEMM: C[128,128] += A_smem[128,128] @ B_glb[128,ldb] ----
// Thread (tx,ty) in 16x16 grid owns 8x8 C tile: rows ty*8.., cols tx*8..
__device__ __forceinline__ void gemm1(const float* __restrict__ A,
                                      const float* __restrict__ B,
                                      int ldb,
                                      float* __restrict__ acc,
                                      int tx, int ty) {
    const float* Ar = A + ty * 8 * SST;
    const float* Bp = B + tx * 8;
#pragma unroll 2
    for (int k4 = 0; k4 < 128; k4 += 4) {
        float4 a4[8];
#pragma unroll
        for (int i = 0; i < 8; ++i)
            a4[i] = *(const float4*)(Ar + i * SST + k4);
        float4 b0[4], b1[4];
#pragma unroll
        for (int kk = 0; kk < 4; ++kk) {
            b0[kk] = *(const float4*)(Bp + (k4 + kk) * ldb);
            b1[kk] = *(const float4*)(Bp + (k4 + kk) * ldb + 4);
        }
#pragma unroll
        for (int kk = 0; kk < 4; ++kk) {
            float b[8] = {b0[kk].x, b0[kk].y, b0[kk].z, b0[kk].w,
                          b1[kk].x, b1[kk].y, b1[kk].z, b1[kk].w};
#pragma unroll
            for (int i = 0; i < 8; ++i) {
                float a = (kk == 0) ? a4[i].x : (kk == 1) ? a4[i].y
                         : (kk == 2) ? a4[i].z : a4[i].w;
#pragma unroll
                for (int j = 0; j < 8; ++j)
                    acc[i * 8 + j] = fmaf(a, b[j], acc[i * 8 + j]);
            }
        }
    }
}

__device__ __forceinline__ float sigmoidf_(float x) {
    return 1.0f / (1.0f + expf(-x));
}

// ---------------- the fused GNN kernel: one CTA per (b,s) ----------------
__global__ void __launch_bounds__(256, 1)
gnn_main(const int* __restrict__ input_var,
         const float* __restrict__ adj,
         const float* __restrict__ emb,
         const float* __restrict__ b_ih,
         const float* __restrict__ b_hh,
         const float* __restrict__ mb1,
         const float* __restrict__ mb2,
         const float* __restrict__ mW3,
         const float* __restrict__ mb3,
         float* __restrict__ out) {
    extern __shared__ float sm[];
    float* nf = sm;                       // [128][SST] node features (persistent)
    float* sb = nf + LDIM * SST;          // [128][SST] s = A@nf / h1
    float* Rb = sb + LDIM * SST;          // [128][SST] r -> n / h2
    unsigned* mask = (unsigned*)(Rb + LDIM * SST);  // [128][4] adjacency bitmask
    float* deg = (float*)(mask + LDIM * 4);         // [128] row degrees

    const int tid = threadIdx.x;
    const int tx = tid & 15, ty = tid >> 4;
    const int lane = tid & 31, warp = tid >> 5;
    const int bs = blockIdx.x;
    const int row0 = ty * 8, col0 = tx * 8;

    // ---- embedding gather: nf[l][:] = emb[input_var[bs][l]][:]
    {
        const int* iv = input_var + bs * LDIM;
        for (int r = 0; r < 16; ++r) {
            int l = warp * 16 + r;
            int idx = iv[l];
            float4 v = ((const float4*)(emb + (size_t)idx * HDIM))[lane];
            *(float4*)(nf + l * SST + lane * 4) = v;
        }
    }

    // ---- adjacency -> bitmask (each thread builds 2 of the 512 words)
    {
        const float4* ab = (const float4*)(adj + (size_t)bs * LDIM * LDIM);
#pragma unroll
        for (int ww = 0; ww < 2; ++ww) {
            int w = tid * 2 + ww;
            int l = w >> 2, part = w & 3;
            const float4* p = ab + (l * LDIM + part * 32) / 4;
            unsigned m = 0;
#pragma unroll
            for (int q = 0; q < 8; ++q) {
                float4 v = p[q];
                m |= (v.x > 0.5f ? 1u : 0u) << (q * 4 + 0);
                m |= (v.y > 0.5f ? 1u : 0u) << (q * 4 + 1);
                m |= (v.z > 0.5f ? 1u : 0u) << (q * 4 + 2);
                m |= (v.w > 0.5f ? 1u : 0u) << (q * 4 + 3);
            }
            mask[w] = m;
        }
    }
    __syncthreads();
    if (tid < LDIM) {
        deg[tid] = (float)(__popc(mask[tid * 4 + 0]) + __popc(mask[tid * 4 + 1]) +
                           __popc(mask[tid * 4 + 2]) + __popc(mask[tid * 4 + 3]));
    }
    __syncthreads();

    float acc[64], accB[64];

    // ---- 10 GRU iterations, fully in SMEM ----
    for (int it = 0; it < NUM_LOOP; ++it) {
        // s = A @ nf via bitmask gather (warp owns 16 rows; lane owns 4 h cols)
        for (int r = 0; r < 16; ++r) {
            int l = warp * 16 + r;
            float4 a = make_float4(0.f, 0.f, 0.f, 0.f);
#pragma unroll
            for (int w4 = 0; w4 < 4; ++w4) {
                unsigned m = mask[l * 4 + w4];
                while (m) {
                    int c = w4 * 32 + __ffs((int)m) - 1;
                    m &= m - 1;
                    float4 v = *(const float4*)(nf + c * SST + lane * 4);
                    a.x += v.x; a.y += v.y; a.z += v.z; a.w += v.w;
                }
            }
            *(float4*)(sb + l * SST + lane * 4) = a;
        }
        __syncthreads();

        // ---- R gate: r = sigmoid(s@G_r + deg*u_r + b_ih_r + nf@Whh_r + b_hh_r)
#pragma unroll
        for (int i = 0; i < 64; ++i) acc[i] = 0.f;
        gemm1(sb, g_Gt + 0, 384, acc, tx, ty);
        gemm1(nf, g_Whht + 0, 384, acc, tx, ty);
#pragma unroll
        for (int i = 0; i < 8; ++i) {
            int l = row0 + i;
            float dg = deg[l];
#pragma unroll
            for (int j = 0; j < 8; ++j) {
                int h = col0 + j;
                float v = acc[i * 8 + j] + dg * g_u[h] + b_ih[h] + b_hh[h];
                Rb[l * SST + h] = sigmoidf_(v);
            }
        }

        // ---- n gate: n = tanh( (s@G_n + deg*u_n + b_ih_n) + r * (nf@Whh_n + b_hh_n) )
#pragma unroll
        for (int i = 0; i < 64; ++i) { acc[i] = 0.f; accB[i] = 0.f; }
        gemm1(sb, g_Gt + 256, 384, acc, tx, ty);
        gemm1(nf, g_Whht + 256, 384, accB, tx, ty);
#pragma unroll
        for (int i = 0; i < 8; ++i) {
            int l = row0 + i;
            float dg = deg[l];
#pragma unroll
            for (int j = 0; j < 8; ++j) {
                int h = col0 + j;
                float ni = acc[i * 8 + j] + dg * g_u[256 + h] + b_ih[256 + h];
                float hn = accB[i * 8 + j] + b_hh[256 + h];
                float r = Rb[l * SST + h];          // same-thread coords: no race
                Rb[l * SST + h] = tanhf(ni + r * hn);  // overwrite r with n
            }
        }

        // ---- Z gate + state update: nf = n + z*(nf - n)
#pragma unroll
        for (int i = 0; i < 64; ++i) acc[i] = 0.f;
        gemm1(sb, g_Gt + 128, 384, acc, tx, ty);
        gemm1(nf, g_Whht + 128, 384, acc, tx, ty);
        __syncthreads();  // all reads of nf/sb complete before nf is overwritten
#pragma unroll
        for (int i = 0; i < 8; ++i) {
            int l = row0 + i;
            float dg = deg[l];
#pragma unroll
            for (int j = 0; j < 8; ++j) {
                int h = col0 + j;
                float v = acc[i * 8 + j] + dg * g_u[128 + h] + b_ih[128 + h] + b_hh[128 + h];
                float z = sigmoidf_(v);
                float n = Rb[l * SST + h];
                float old = nf[l * SST + h];
                nf[l * SST + h] = n + z * (old - n);
            }
        }
        __syncthreads();
    }

    // ---- mention MLP: h1 = tanh(nf@mW1^T+b1); h2 = tanh(h1@mW2^T+b2); tanh(h2@mW3^T+b3)
#pragma unroll
    for (int i = 0; i < 64; ++i) acc[i] = 0.f;
    gemm1(nf, g_m1t, 128, acc, tx, ty);
#pragma unroll
    for (int i = 0; i < 8; ++i)
#pragma unroll
        for (int j = 0; j < 8; ++j)
            sb[(row0 + i) * SST + col0 + j] = tanhf(acc[i * 8 + j] + mb1[col0 + j]);
    __syncthreads();

#pragma unroll
    for (int i = 0; i < 64; ++i) acc[i] = 0.f;
    gemm1(sb, g_m2t, 128, acc, tx, ty);
#pragma unroll
    for (int i = 0; i < 8; ++i)
#pragma unroll
        for (int j = 0; j < 8; ++j)
            Rb[(row0 + i) * SST + col0 + j] = tanhf(acc[i * 8 + j] + mb2[col0 + j]);
    __syncthreads();

    if (tid < LDIM) {
        float a = mb3[0];
#pragma unroll 4
        for (int h = 0; h < HDIM; ++h)
            a = fmaf(Rb[tid * SST + h], mW3[h], a);
        out[bs * LDIM + tid] = tanhf(a);
    }
}

// ---------------- launch ----------------
extern "C" void kernel_launch(void* const* d_in, const int* in_sizes, int n_in,
                              void* d_out, int out_size) {
    const int*   input_var = (const int*)  d_in[0];
    const float* adjacency = (const float*)d_in[1];
    const float* emb       = (const float*)d_in[2];
    const float* gnn_w     = (const float*)d_in[3];
    const float* gnn_b     = (const float*)d_in[4];
    const float* W_ih      = (const float*)d_in[5];
    const float* W_hh      = (const float*)d_in[6];
    const float* b_ih      = (const float*)d_in[7];
    const float* b_hh      = (const float*)d_in[8];
    const float* mW1       = (const float*)d_in[9];
    const float* mb1       = (const float*)d_in[10];
    const float* mW2       = (const float*)d_in[11];
    const float* mb2       = (const float*)d_in[12];
    const float* mW3       = (const float*)d_in[13];
    const float* mb3       = (const float*)d_in[14];
    float* out = (float*)d_out;

    // prep: fused weight products + transposes (deterministic, recomputed every call)
    prep_gemm<<<(128 * 384 + 255) / 256, 256>>>(gnn_w, W_ih, gnn_b);
    prep_trans<<<(128 * 384 + 2 * 128 * 128 + 255) / 256, 256>>>(W_hh, mW1, mW2);

    const int smem_bytes = (3 * LDIM * SST) * 4 + LDIM * 4 * 4 + LDIM * 4;
    cudaFuncSetAttribute(gnn_main, cudaFuncAttributeMaxDynamicSharedMemorySize, smem_bytes);
    gnn_main<<<NBS, 256, smem_bytes>>>(input_var, adjacency, emb,
                                       b_ih, b_hh, mb1, mb2, mW3, mb3, out);
}